// round 2
// baseline (speedup 1.0000x reference)
#include <cuda_runtime.h>

// FFTConv1d: y[b,o,t] = sum_{i,k} W[o,i,k] * x[b,i,t+63-k]  (zero-padded x)
// B=8, CIN=COUT=64, T=16384, K=127, crop start = 63 ('same', centered)

#define B_      8
#define CIN     64
#define COUT    64
#define T_      16384
#define KW      127
#define PAD     63
#define TT      128        // t-tile per block
#define RR      16         // outputs per thread
#define NGROUP  (TT / RR)  // 8 t-groups
#define NTHREADS (COUT * NGROUP)  // 512
#define WSTRIDE (KW + 2)   // 129, odd stride -> conflict-free lane reads

__global__ __launch_bounds__(NTHREADS, 2)
void conv1d_direct_kernel(const float* __restrict__ x,
                          const float* __restrict__ W,
                          float* __restrict__ y) {
    __shared__ float xsh[TT + 128];          // window: [t0-63, t0+TT+63)
    __shared__ float Wsh[COUT * WSTRIDE];    // W[:, i, :] staged per input ch

    const int b   = blockIdx.y;
    const int t0  = blockIdx.x * TT;
    const int tid = threadIdx.x;
    const int o   = tid & 63;                // warp lanes 0..31 -> o 0..31 (same g)
    const int g   = tid >> 6;                // t-group 0..7

    float acc[RR];
    #pragma unroll
    for (int r = 0; r < RR; r++) acc[r] = 0.f;

    for (int i = 0; i < CIN; i++) {
        // --- stage x window for channel i (zero padded) ---
        for (int j = tid; j < TT + 126; j += NTHREADS) {
            int t = t0 - PAD + j;
            xsh[j] = (t >= 0 && t < T_) ? x[(b * CIN + i) * T_ + t] : 0.f;
        }
        // --- stage W[:, i, :] ---
        for (int m = tid; m < COUT * KW; m += NTHREADS) {
            int oo = m / KW;
            int kk = m - oo * KW;
            Wsh[oo * WSTRIDE + kk] = W[(oo * CIN + i) * KW + kk];
        }
        __syncthreads();

        const float* wrow = &Wsh[o * WSTRIDE];
        const float* xrow = &xsh[g * RR];
        // acc[r] += sum_k wrow[k] * xrow[r + 126 - k]

        #pragma unroll 1
        for (int k = 0; k < 124; k += 4) {
            const float w0 = wrow[k], w1 = wrow[k + 1],
                        w2 = wrow[k + 2], w3 = wrow[k + 3];
            const int base = 123 - k;  // pairs with w3
            float xv0 = xrow[base], xv1 = xrow[base + 1], xv2 = xrow[base + 2];
            #pragma unroll
            for (int r = 0; r < RR; r++) {
                const float xv3 = xrow[base + 3 + r];   // 1 LDS per 4 MACs
                acc[r] += w3 * xv0;
                acc[r] += w2 * xv1;
                acc[r] += w1 * xv2;
                acc[r] += w0 * xv3;
                xv0 = xv1; xv1 = xv2; xv2 = xv3;        // renamed away by unroll
            }
        }
        // tail: k = 124, 125, 126
        {
            const float w0 = wrow[124], w1 = wrow[125], w2 = wrow[126];
            float xv0 = xrow[0], xv1 = xrow[1];
            #pragma unroll
            for (int r = 0; r < RR; r++) {
                const float xv2 = xrow[2 + r];
                acc[r] += w2 * xv0;
                acc[r] += w1 * xv1;
                acc[r] += w0 * xv2;
                xv0 = xv1; xv1 = xv2;
            }
        }
        __syncthreads();
    }

    // --- write 16 contiguous floats per thread as 4x float4 ---
    float* yp = &y[(b * COUT + o) * T_ + t0 + g * RR];
    #pragma unroll
    for (int r4 = 0; r4 < RR; r4 += 4) {
        float4 v = make_float4(acc[r4], acc[r4 + 1], acc[r4 + 2], acc[r4 + 3]);
        *reinterpret_cast<float4*>(yp + r4) = v;
    }
}

extern "C" void kernel_launch(void* const* d_in, const int* in_sizes, int n_in,
                              void* d_out, int out_size) {
    const float* x = (const float*)d_in[0];   // [B, CIN, T]
    const float* W = (const float*)d_in[1];   // [COUT, CIN, K]
    float* y       = (float*)d_out;           // [B, COUT, T]
    (void)in_sizes; (void)n_in; (void)out_size;

    dim3 grid(T_ / TT, B_);                    // 128 x 8 = 1024 blocks
    conv1d_direct_kernel<<<grid, NTHREADS>>>(x, W, y);
}

// round 6
// speedup vs baseline: 3.7682x; 3.7682x over previous
#include <cuda_runtime.h>
#include <cuda_fp16.h>
#include <cstdint>

#define TB     8
#define NCH    64
#define TLEN   16384
#define KW     127
#define TP     16512
#define TILE_T 256
#define XR     384
#define XB     (XR * 128)      // 48 KB per half
#define WSTG   16384           // per-tap W stage: hi 8K + lo 8K
#define NST    4
#define NTH    256
#define SMEMSZ (1024 + 2 * XB + NST * WSTG)   // 164864

// fp16 hi/lo decompositions, transposed layouts
__device__ __align__(16) __half g_xh[(size_t)TB * TP * NCH];   // [B][TP][C]
__device__ __align__(16) __half g_xl[(size_t)TB * TP * NCH];
__device__ __align__(16) __half g_wh[(size_t)KW * NCH * NCH];  // [K][O][C]
__device__ __align__(16) __half g_wl[(size_t)KW * NCH * NCH];

__device__ __forceinline__ uint32_t smem_u32(const void* p) {
    uint32_t a;
    asm("{ .reg .u64 t; cvta.to.shared.u64 t, %1; cvt.u32.u64 %0, t; }" : "=r"(a) : "l"(p));
    return a;
}
__device__ __forceinline__ void cp16(uint32_t d, const void* s) {
    asm volatile("cp.async.cg.shared.global [%0], [%1], 16;" :: "r"(d), "l"(s));
}
#define CP_COMMIT() asm volatile("cp.async.commit_group;" ::: "memory")
#define CP_WAIT2()  asm volatile("cp.async.wait_group 2;" ::: "memory")

#define LDSM4(r, a)                                                            \
    asm volatile("ldmatrix.sync.aligned.m8n8.x4.shared.b16 {%0,%1,%2,%3}, [%4];" \
                 : "=r"((r)[0]), "=r"((r)[1]), "=r"((r)[2]), "=r"((r)[3]) : "r"(a))
#define LDSM2(r, a)                                                            \
    asm volatile("ldmatrix.sync.aligned.m8n8.x2.shared.b16 {%0,%1}, [%2];"     \
                 : "=r"((r)[0]), "=r"((r)[1]) : "r"(a))
#define MMA(c, A, Bf)                                                          \
    asm volatile("mma.sync.aligned.m16n8k16.row.col.f32.f16.f16.f32 "          \
                 "{%0,%1,%2,%3},{%4,%5,%6,%7},{%8,%9},{%0,%1,%2,%3};"          \
                 : "+f"((c)[0]), "+f"((c)[1]), "+f"((c)[2]), "+f"((c)[3])      \
                 : "r"((A)[0]), "r"((A)[1]), "r"((A)[2]), "r"((A)[3]),         \
                   "r"((Bf)[0]), "r"((Bf)[1]))

// stage W[k] (hi+lo) into smem stage with xor-swizzled rows (o=row, 128B/row)
__device__ __forceinline__ void stage_w(int k, uint32_t dst, int tid) {
    const uint4* wh = (const uint4*)g_wh + (size_t)k * 512;   // 512 x 16B per half
    const uint4* wl = (const uint4*)g_wl + (size_t)k * 512;
    #pragma unroll
    for (int jj = 0; jj < 2; jj++) {
        const int ch = tid + (jj << 8);                       // 0..511
        const uint32_t row = (uint32_t)(ch >> 3), c = (uint32_t)(ch & 7);
        const uint32_t sw = row * 128 + ((c ^ (row & 7)) << 4);
        cp16(dst + sw, wh + ch);
        cp16(dst + 8192 + sw, wl + ch);
    }
}

// ------------- prep x: fp32 [B][C][T] -> fp16 hi/lo [B][TP][C] ---------------
__global__ void __launch_bounds__(256) prep_x(const float* __restrict__ x) {
    __shared__ float tile[NCH][129];
    const int b = blockIdx.y, g0 = blockIdx.x << 7, tid = threadIdx.x;
    for (int e = tid; e < NCH * 128; e += 256) {
        const int i = e >> 7, tl = e & 127, t = g0 + tl - 63;
        tile[i][tl] = (t >= 0 && t < TLEN) ? x[((size_t)b * NCH + i) * TLEN + t] : 0.f;
    }
    __syncthreads();
    __half2* oh = (__half2*)g_xh + ((size_t)b * TP + g0) * 32;
    __half2* ol = (__half2*)g_xl + ((size_t)b * TP + g0) * 32;
    for (int e = tid; e < 128 * 32; e += 256) {
        const int gl = e >> 5, j = e & 31;
        const float v0 = tile[2 * j][gl], v1 = tile[2 * j + 1][gl];
        const __half h0 = __float2half_rn(v0), h1 = __float2half_rn(v1);
        const __half l0 = __float2half_rn(v0 - __half2float(h0));
        const __half l1 = __float2half_rn(v1 - __half2float(h1));
        oh[(size_t)gl * 32 + j] = __halves2half2(h0, h1);
        ol[(size_t)gl * 32 + j] = __halves2half2(l0, l1);
    }
}
// ------------- prep W: fp32 [O][C][K] -> fp16 hi/lo [K][O][C] ----------------
__global__ void __launch_bounds__(256) prep_w(const float* __restrict__ W) {
    const int idx = blockIdx.x * 256 + threadIdx.x;
    if (idx >= KW * NCH * 32) return;
    const int j = idx & 31, o = (idx >> 5) & 63, k = idx >> 11;
    const float v0 = W[((size_t)o * NCH + 2 * j) * KW + k];
    const float v1 = W[((size_t)o * NCH + 2 * j + 1) * KW + k];
    const __half h0 = __float2half_rn(v0), h1 = __float2half_rn(v1);
    const __half l0 = __float2half_rn(v0 - __half2float(h0));
    const __half l1 = __float2half_rn(v1 - __half2float(h1));
    ((__half2*)g_wh)[idx] = __halves2half2(h0, h1);
    ((__half2*)g_wl)[idx] = __halves2half2(l0, l1);
}
// ------------- main: grid (64, 8), 256 threads, 1 CTA/SM ---------------------
__global__ void __launch_bounds__(NTH, 1)
conv_mma(float* __restrict__ y) {
    extern __shared__ char smraw[];
    const uint32_t raw = smem_u32(smraw);
    const uint32_t xhA = (raw + 1023) & ~1023u;
    const uint32_t xlA = xhA + XB;
    const uint32_t wA  = xlA + XB;
    const int tid = threadIdx.x, wid = tid >> 5, lane = tid & 31;
    const int b = blockIdx.y, t0 = blockIdx.x * TILE_T;

    // ---- stage x window rows [t0, t0+XR) once (xor-swizzled) ----
    {
        const uint4* sh = (const uint4*)g_xh + ((size_t)b * TP + t0) * 8;
        const uint4* sl = (const uint4*)g_xl + ((size_t)b * TP + t0) * 8;
        for (int e = tid; e < XR * 8; e += NTH) {
            const uint32_t r = (uint32_t)(e >> 3), c = (uint32_t)(e & 7);
            const uint32_t sw = r * 128 + ((c ^ (r & 7)) << 4);
            cp16(xhA + sw, sh + e);
            cp16(xlA + sw, sl + e);
        }
        CP_COMMIT();
    }
    // ---- prologue W taps 0..2 ----
    #pragma unroll
    for (int p = 0; p < 3; p++) {
        stage_w(p, wA + (uint32_t)(p * WSTG), tid);
        CP_COMMIT();
    }

    float acc[4][4][4];
    #pragma unroll
    for (int mb = 0; mb < 4; mb++)
        #pragma unroll
        for (int nb = 0; nb < 4; nb++)
            #pragma unroll
            for (int q = 0; q < 4; q++) acc[mb][nb][q] = 0.f;

    const int rA = lane & 15, cA = lane >> 4;        // A (W) lane row/chunk
    const int rB = lane & 7,  cB = (lane >> 3) & 1;  // B (x) lane row/chunk

    for (int n = 0; n < KW; n++) {
        CP_WAIT2();
        __syncthreads();
        if (n + 3 < KW) stage_w(n + 3, wA + (uint32_t)(((n + 3) & 3) * WSTG), tid);
        CP_COMMIT();

        const uint32_t stg = wA + (uint32_t)((n & 3) * WSTG);
        const int rbase = (126 - n) + wid * 32 + rB;

        #pragma unroll
        for (int kc = 0; kc < 4; kc++) {
            uint32_t Ah[4][4], Al[4][4], Bh[4][2], Bl[4][2];
            #pragma unroll
            for (int mb = 0; mb < 4; mb++) {
                const uint32_t row = (uint32_t)(mb * 16 + rA);
                const uint32_t a = stg + row * 128 + ((((uint32_t)(kc * 2 + cA)) ^ (row & 7)) << 4);
                LDSM4(Ah[mb], a);
                LDSM4(Al[mb], a + 8192);
            }
            #pragma unroll
            for (int nb = 0; nb < 4; nb++) {
                const uint32_t row = (uint32_t)(rbase + nb * 8);
                const uint32_t off = row * 128 + ((((uint32_t)(kc * 2 + cB)) ^ (row & 7)) << 4);
                LDSM2(Bh[nb], xhA + off);
                LDSM2(Bl[nb], xlA + off);
            }
            #pragma unroll
            for (int mb = 0; mb < 4; mb++)
                #pragma unroll
                for (int nb = 0; nb < 4; nb++) {
                    MMA(acc[mb][nb], Ah[mb], Bh[nb]);
                    MMA(acc[mb][nb], Ah[mb], Bl[nb]);
                    MMA(acc[mb][nb], Al[mb], Bh[nb]);
                }
        }
    }

    // ---- epilogue: D[o, t] -> y[b][o][t] ----
    const int g = lane >> 2, q = lane & 3;
    #pragma unroll
    for (int mb = 0; mb < 4; mb++) {
        #pragma unroll
        for (int nb = 0; nb < 4; nb++) {
            const int o = mb * 16 + g;
            const int t = t0 + wid * 32 + nb * 8 + q * 2;
            float2 v0 = make_float2(acc[mb][nb][0], acc[mb][nb][1]);
            float2 v1 = make_float2(acc[mb][nb][2], acc[mb][nb][3]);
            *reinterpret_cast<float2*>(&y[((size_t)b * NCH + o) * TLEN + t]) = v0;
            *reinterpret_cast<float2*>(&y[((size_t)b * NCH + o + 8) * TLEN + t]) = v1;
        }
    }
}

extern "C" void kernel_launch(void* const* d_in, const int* in_sizes, int n_in,
                              void* d_out, int out_size) {
    const float* x = (const float*)d_in[0];
    const float* W = (const float*)d_in[1];
    float* y = (float*)d_out;
    (void)in_sizes; (void)n_in; (void)out_size;
    cudaFuncSetAttribute(conv_mma, cudaFuncAttributeMaxDynamicSharedMemorySize, SMEMSZ);
    prep_x<<<dim3(TP / 128, TB), 256>>>(x);
    prep_w<<<(KW * NCH * 32 + 255) / 256, 256>>>(W);
    conv_mma<<<dim3(TLEN / TILE_T, TB), 256, SMEMSZ>>>(y);
}

// round 7
// speedup vs baseline: 5.6695x; 1.5046x over previous
#include <cuda_runtime.h>
#include <cuda_fp16.h>
#include <cstdint>

#define TB     8
#define NCH    64
#define TLEN   16384
#define KW     127
#define TP     16512
#define TILE_T 256
#define XR     384
#define XB     (XR * 128)          // 48 KB per half
#define TSTG   8192                // per-tap W stage (wh only)
#define GSTG   (4 * TSTG)          // 4-tap group = 32 KB
#define NSLOT  3
#define NGRP   32                  // ceil(127/4)
#define NTH    256
#define SMEMSZ (1024 + 2 * XB + NSLOT * GSTG)   // 197632

__device__ __align__(16) __half g_xh[(size_t)TB * TP * NCH];   // [B][TP][C] hi
__device__ __align__(16) __half g_xl[(size_t)TB * TP * NCH];   // [B][TP][C] lo
__device__ __align__(16) __half g_wh[(size_t)KW * NCH * NCH];  // [K][O][C] hi

__device__ __forceinline__ uint32_t smem_u32(const void* p) {
    uint32_t a;
    asm("{ .reg .u64 t; cvta.to.shared.u64 t, %1; cvt.u32.u64 %0, t; }" : "=r"(a) : "l"(p));
    return a;
}
__device__ __forceinline__ void cp16(uint32_t d, const void* s) {
    asm volatile("cp.async.cg.shared.global [%0], [%1], 16;" :: "r"(d), "l"(s));
}
#define CP_COMMIT() asm volatile("cp.async.commit_group;" ::: "memory")
#define CP_WAIT1()  asm volatile("cp.async.wait_group 1;" ::: "memory")

#define LDSM4(r, a)                                                            \
    asm volatile("ldmatrix.sync.aligned.m8n8.x4.shared.b16 {%0,%1,%2,%3}, [%4];" \
                 : "=r"((r)[0]), "=r"((r)[1]), "=r"((r)[2]), "=r"((r)[3]) : "r"(a))
#define LDSM2(r, a)                                                            \
    asm volatile("ldmatrix.sync.aligned.m8n8.x2.shared.b16 {%0,%1}, [%2];"     \
                 : "=r"((r)[0]), "=r"((r)[1]) : "r"(a))
#define MMA(c, A, Bf)                                                          \
    asm volatile("mma.sync.aligned.m16n8k16.row.col.f32.f16.f16.f32 "          \
                 "{%0,%1,%2,%3},{%4,%5,%6,%7},{%8,%9},{%0,%1,%2,%3};"          \
                 : "+f"((c)[0]), "+f"((c)[1]), "+f"((c)[2]), "+f"((c)[3])      \
                 : "r"((A)[0]), "r"((A)[1]), "r"((A)[2]), "r"((A)[3]),         \
                   "r"((Bf)[0]), "r"((Bf)[1]))

// stage W group g (taps 4g..4g+3, wh only) into slot base, xor-swizzled rows
__device__ __forceinline__ void stage_wg(int g, uint32_t dst, int tid) {
    #pragma unroll
    for (int q = 0; q < 4; q++) {
        const int k = 4 * g + q;
        if (k < KW) {
            const uint4* wh = (const uint4*)g_wh + (size_t)k * 512;
            const uint32_t tdst = dst + (uint32_t)(q * TSTG);
            #pragma unroll
            for (int jj = 0; jj < 2; jj++) {
                const int ch = tid + (jj << 8);
                const uint32_t row = (uint32_t)(ch >> 3), c = (uint32_t)(ch & 7);
                cp16(tdst + row * 128 + ((c ^ (row & 7)) << 4), wh + ch);
            }
        }
    }
}

// ------------- prep x: fp32 [B][C][T] -> fp16 hi/lo [B][TP][C] ---------------
__global__ void __launch_bounds__(256) prep_x(const float* __restrict__ x) {
    __shared__ float tile[NCH][129];
    const int b = blockIdx.y, g0 = blockIdx.x << 7, tid = threadIdx.x;
    for (int e = tid; e < NCH * 128; e += 256) {
        const int i = e >> 7, tl = e & 127, t = g0 + tl - 63;
        tile[i][tl] = (t >= 0 && t < TLEN) ? x[((size_t)b * NCH + i) * TLEN + t] : 0.f;
    }
    __syncthreads();
    __half2* oh = (__half2*)g_xh + ((size_t)b * TP + g0) * 32;
    __half2* ol = (__half2*)g_xl + ((size_t)b * TP + g0) * 32;
    for (int e = tid; e < 128 * 32; e += 256) {
        const int gl = e >> 5, j = e & 31;
        const float v0 = tile[2 * j][gl], v1 = tile[2 * j + 1][gl];
        const __half h0 = __float2half_rn(v0), h1 = __float2half_rn(v1);
        const __half l0 = __float2half_rn(v0 - __half2float(h0));
        const __half l1 = __float2half_rn(v1 - __half2float(h1));
        oh[(size_t)gl * 32 + j] = __halves2half2(h0, h1);
        ol[(size_t)gl * 32 + j] = __halves2half2(l0, l1);
    }
}
// ------------- prep W: fp32 [O][C][K] -> fp16 hi [K][O][C] -------------------
__global__ void __launch_bounds__(256) prep_w(const float* __restrict__ W) {
    const int idx = blockIdx.x * 256 + threadIdx.x;
    if (idx >= KW * NCH * 32) return;
    const int j = idx & 31, o = (idx >> 5) & 63, k = idx >> 11;
    const float v0 = W[((size_t)o * NCH + 2 * j) * KW + k];
    const float v1 = W[((size_t)o * NCH + 2 * j + 1) * KW + k];
    ((__half2*)g_wh)[idx] = __halves2half2(__float2half_rn(v0), __float2half_rn(v1));
}
// ------------- main: grid (64, 8), 256 threads, 1 CTA/SM ---------------------
__global__ void __launch_bounds__(NTH, 1)
conv_mma(float* __restrict__ y) {
    extern __shared__ char smraw[];
    const uint32_t raw = smem_u32(smraw);
    const uint32_t xhA = (raw + 1023) & ~1023u;
    const uint32_t xlA = xhA + XB;
    const uint32_t wA  = xlA + XB;
    const int tid = threadIdx.x, wid = tid >> 5, lane = tid & 31;
    const int b = blockIdx.y, t0 = blockIdx.x * TILE_T;

    // ---- stage x window rows [t0, t0+XR) once (xor-swizzled) ----  commit c0
    {
        const uint4* sh = (const uint4*)g_xh + ((size_t)b * TP + t0) * 8;
        const uint4* sl = (const uint4*)g_xl + ((size_t)b * TP + t0) * 8;
        for (int e = tid; e < XR * 8; e += NTH) {
            const uint32_t r = (uint32_t)(e >> 3), c = (uint32_t)(e & 7);
            const uint32_t sw = r * 128 + ((c ^ (r & 7)) << 4);
            cp16(xhA + sw, sh + e);
            cp16(xlA + sw, sl + e);
        }
        CP_COMMIT();
    }
    // ---- prologue: groups 0,1 (commits c1, c2) ----
    stage_wg(0, wA, tid);               CP_COMMIT();
    stage_wg(1, wA + GSTG, tid);        CP_COMMIT();

    float acc[4][4][4];
    #pragma unroll
    for (int mb = 0; mb < 4; mb++)
        #pragma unroll
        for (int nb = 0; nb < 4; nb++)
            #pragma unroll
            for (int q = 0; q < 4; q++) acc[mb][nb][q] = 0.f;

    const int rA = lane & 15, cA = lane >> 4;
    const int rB = lane & 7,  cB = (lane >> 3) & 1;

    for (int g = 0; g < NGRP; g++) {
        CP_WAIT1();          // group g resident (all but newest commit done)
        __syncthreads();     // cross-warp visibility + retire group g-1 reads
        if (g + 2 < NGRP)    // slot (g+2)%3 held group g-1: safe to overwrite
            stage_wg(g + 2, wA + (uint32_t)(((g + 2) % NSLOT) * GSTG), tid);
        CP_COMMIT();         // one commit per iter keeps wait accounting fixed

        const uint32_t slot = wA + (uint32_t)((g % NSLOT) * GSTG);
        const int ntaps = (g == NGRP - 1) ? 3 : 4;
        for (int q = 0; q < ntaps; q++) {
            const int n = 4 * g + q;
            const uint32_t stg = slot + (uint32_t)(q * TSTG);
            const int rbase = (126 - n) + wid * 32 + rB;
            #pragma unroll
            for (int kc = 0; kc < 4; kc++) {
                uint32_t Ah[4][4], Bh[4][2], Bl[4][2];
                #pragma unroll
                for (int mb = 0; mb < 4; mb++) {
                    const uint32_t row = (uint32_t)(mb * 16 + rA);
                    LDSM4(Ah[mb], stg + row * 128 +
                                  ((((uint32_t)(kc * 2 + cA)) ^ (row & 7)) << 4));
                }
                #pragma unroll
                for (int nb = 0; nb < 4; nb++) {
                    const uint32_t row = (uint32_t)(rbase + nb * 8);
                    const uint32_t off = row * 128 +
                        ((((uint32_t)(kc * 2 + cB)) ^ (row & 7)) << 4);
                    LDSM2(Bh[nb], xhA + off);
                    LDSM2(Bl[nb], xlA + off);
                }
                #pragma unroll
                for (int mb = 0; mb < 4; mb++)
                    #pragma unroll
                    for (int nb = 0; nb < 4; nb++) {
                        MMA(acc[mb][nb], Ah[mb], Bh[nb]);   // xh * wh
                        MMA(acc[mb][nb], Ah[mb], Bl[nb]);   // xl * wh
                    }
            }
        }
    }

    // ---- epilogue: D[o, t] -> y[b][o][t] ----
    const int gq = lane >> 2, qq = lane & 3;
    #pragma unroll
    for (int mb = 0; mb < 4; mb++) {
        #pragma unroll
        for (int nb = 0; nb < 4; nb++) {
            const int o = mb * 16 + gq;
            const int t = t0 + wid * 32 + nb * 8 + qq * 2;
            float2 v0 = make_float2(acc[mb][nb][0], acc[mb][nb][1]);
            float2 v1 = make_float2(acc[mb][nb][2], acc[mb][nb][3]);
            *reinterpret_cast<float2*>(&y[((size_t)b * NCH + o) * TLEN + t]) = v0;
            *reinterpret_cast<float2*>(&y[((size_t)b * NCH + o + 8) * TLEN + t]) = v1;
        }
    }
}

extern "C" void kernel_launch(void* const* d_in, const int* in_sizes, int n_in,
                              void* d_out, int out_size) {
    const float* x = (const float*)d_in[0];
    const float* W = (const float*)d_in[1];
    float* y = (float*)d_out;
    (void)in_sizes; (void)n_in; (void)out_size;
    cudaFuncSetAttribute(conv_mma, cudaFuncAttributeMaxDynamicSharedMemorySize, SMEMSZ);
    prep_x<<<dim3(TP / 128, TB), 256>>>(x);
    prep_w<<<(KW * NCH * 32 + 255) / 256, 256>>>(W);
    conv_mma<<<dim3(TLEN / TILE_T, TB), 256, SMEMSZ>>>(y);
}

// round 9
// speedup vs baseline: 10.2115x; 1.8011x over previous
#include <cuda_runtime.h>
#include <cuda_fp16.h>
#include <cstdint>

#define TB     8
#define NCH    64
#define TLEN   16384
#define KW     127
#define TP     16512
#define TILE_T 256
#define XR     384
#define XB     (XR * 128)          // 48 KB (xh only)
#define TSTG   8192                // per-tap W stage (wh only)
#define GSTG   (4 * TSTG)          // 4-tap group = 32 KB
#define NSLOT  3
#define NGRP   32                  // ceil(127/4)
#define NTH    256
#define SMEMSZ (1024 + XB + NSLOT * GSTG)   // 148480

__device__ __align__(16) __half g_xh[(size_t)TB * TP * NCH];   // [B][TP][C] hi
__device__ __align__(16) __half g_wh[(size_t)KW * NCH * NCH];  // [K][O][C] hi

__device__ __forceinline__ uint32_t smem_u32(const void* p) {
    uint32_t a;
    asm("{ .reg .u64 t; cvta.to.shared.u64 t, %1; cvt.u32.u64 %0, t; }" : "=r"(a) : "l"(p));
    return a;
}
__device__ __forceinline__ void cp16(uint32_t d, const void* s) {
    asm volatile("cp.async.cg.shared.global [%0], [%1], 16;" :: "r"(d), "l"(s));
}
#define CP_COMMIT() asm volatile("cp.async.commit_group;" ::: "memory")
#define CP_WAIT1()  asm volatile("cp.async.wait_group 1;" ::: "memory")

#define LDSM4(r, a)                                                            \
    asm volatile("ldmatrix.sync.aligned.m8n8.x4.shared.b16 {%0,%1,%2,%3}, [%4];" \
                 : "=r"((r)[0]), "=r"((r)[1]), "=r"((r)[2]), "=r"((r)[3]) : "r"(a))
#define LDSM2(r, a)                                                            \
    asm volatile("ldmatrix.sync.aligned.m8n8.x2.shared.b16 {%0,%1}, [%2];"     \
                 : "=r"((r)[0]), "=r"((r)[1]) : "r"(a))
#define MMA(c, A, Bf)                                                          \
    asm volatile("mma.sync.aligned.m16n8k16.row.col.f32.f16.f16.f32 "          \
                 "{%0,%1,%2,%3},{%4,%5,%6,%7},{%8,%9},{%0,%1,%2,%3};"          \
                 : "+f"((c)[0]), "+f"((c)[1]), "+f"((c)[2]), "+f"((c)[3])      \
                 : "r"((A)[0]), "r"((A)[1]), "r"((A)[2]), "r"((A)[3]),         \
                   "r"((Bf)[0]), "r"((Bf)[1]))

// stage W group g (taps 4g..4g+3) into slot base, xor-swizzled rows
__device__ __forceinline__ void stage_wg(int g, uint32_t dst, int tid) {
    #pragma unroll
    for (int q = 0; q < 4; q++) {
        const int k = 4 * g + q;
        if (k < KW) {
            const uint4* wh = (const uint4*)g_wh + (size_t)k * 512;
            const uint32_t tdst = dst + (uint32_t)(q * TSTG);
            #pragma unroll
            for (int jj = 0; jj < 2; jj++) {
                const int ch = tid + (jj << 8);
                const uint32_t row = (uint32_t)(ch >> 3), c = (uint32_t)(ch & 7);
                cp16(tdst + row * 128 + ((c ^ (row & 7)) << 4), wh + ch);
            }
        }
    }
}

// ------------- prep x: fp32 [B][C][T] -> fp16 hi [B][TP][C] ------------------
__global__ void __launch_bounds__(256) prep_x(const float* __restrict__ x) {
    __shared__ float tile[NCH][129];
    const int b = blockIdx.y, g0 = blockIdx.x << 7, tid = threadIdx.x;
    for (int e = tid; e < NCH * 128; e += 256) {
        const int i = e >> 7, tl = e & 127, t = g0 + tl - 63;
        tile[i][tl] = (t >= 0 && t < TLEN) ? x[((size_t)b * NCH + i) * TLEN + t] : 0.f;
    }
    __syncthreads();
    __half2* oh = (__half2*)g_xh + ((size_t)b * TP + g0) * 32;
    for (int e = tid; e < 128 * 32; e += 256) {
        const int gl = e >> 5, j = e & 31;
        oh[(size_t)gl * 32 + j] = __halves2half2(__float2half_rn(tile[2 * j][gl]),
                                                 __float2half_rn(tile[2 * j + 1][gl]));
    }
}
// ------------- prep W: fp32 [O][C][K] -> fp16 hi [K][O][C] -------------------
__global__ void __launch_bounds__(256) prep_w(const float* __restrict__ W) {
    const int idx = blockIdx.x * 256 + threadIdx.x;
    if (idx >= KW * NCH * 32) return;
    const int j = idx & 31, o = (idx >> 5) & 63, k = idx >> 11;
    const float v0 = W[((size_t)o * NCH + 2 * j) * KW + k];
    const float v1 = W[((size_t)o * NCH + 2 * j + 1) * KW + k];
    ((__half2*)g_wh)[idx] = __halves2half2(__float2half_rn(v0), __float2half_rn(v1));
}
// ------------- main: grid (64, 8), 256 threads, 1 CTA/SM ---------------------
__global__ void __launch_bounds__(NTH, 1)
conv_mma(float* __restrict__ y) {
    extern __shared__ char smraw[];
    const uint32_t raw = smem_u32(smraw);
    const uint32_t xhA = (raw + 1023) & ~1023u;
    const uint32_t wA  = xhA + XB;
    const int tid = threadIdx.x, wid = tid >> 5, lane = tid & 31;
    const int b = blockIdx.y, t0 = blockIdx.x * TILE_T;

    // ---- stage x window rows [t0, t0+XR) once (xor-swizzled) ----  commit c0
    {
        const uint4* sh = (const uint4*)g_xh + ((size_t)b * TP + t0) * 8;
        for (int e = tid; e < XR * 8; e += NTH) {
            const uint32_t r = (uint32_t)(e >> 3), c = (uint32_t)(e & 7);
            cp16(xhA + r * 128 + ((c ^ (r & 7)) << 4), sh + e);
        }
        CP_COMMIT();
    }
    // ---- prologue: groups 0,1 (commits c1, c2) ----
    stage_wg(0, wA, tid);               CP_COMMIT();
    stage_wg(1, wA + GSTG, tid);        CP_COMMIT();

    float acc[4][4][4];
    #pragma unroll
    for (int mb = 0; mb < 4; mb++)
        #pragma unroll
        for (int nb = 0; nb < 4; nb++)
            #pragma unroll
            for (int q = 0; q < 4; q++) acc[mb][nb][q] = 0.f;

    const int rA = lane & 15, cA = lane >> 4;
    const int rB = lane & 7,  cB = (lane >> 3) & 1;

    for (int g = 0; g < NGRP; g++) {
        CP_WAIT1();          // group g resident
        __syncthreads();     // visibility + retire group g-1 reads
        if (g + 2 < NGRP)
            stage_wg(g + 2, wA + (uint32_t)(((g + 2) % NSLOT) * GSTG), tid);
        CP_COMMIT();

        const uint32_t slot = wA + (uint32_t)((g % NSLOT) * GSTG);
        const int ntaps = (g == NGRP - 1) ? 3 : 4;
        for (int q = 0; q < ntaps; q++) {
            const int n = 4 * g + q;
            const uint32_t stg = slot + (uint32_t)(q * TSTG);
            const int rbase = (126 - n) + wid * 32 + rB;
            #pragma unroll
            for (int kc = 0; kc < 4; kc++) {
                uint32_t Ah[4][4], Bh[4][2];
                #pragma unroll
                for (int mb = 0; mb < 4; mb++) {
                    const uint32_t row = (uint32_t)(mb * 16 + rA);
                    LDSM4(Ah[mb], stg + row * 128 +
                                  ((((uint32_t)(kc * 2 + cA)) ^ (row & 7)) << 4));
                }
                #pragma unroll
                for (int nb = 0; nb < 4; nb++) {
                    const uint32_t row = (uint32_t)(rbase + nb * 8);
                    LDSM2(Bh[nb], xhA + row * 128 +
                                  ((((uint32_t)(kc * 2 + cB)) ^ (row & 7)) << 4));
                }
                #pragma unroll
                for (int mb = 0; mb < 4; mb++)
                    #pragma unroll
                    for (int nb = 0; nb < 4; nb++)
                        MMA(acc[mb][nb], Ah[mb], Bh[nb]);
            }
        }
    }

    // ---- epilogue: D[o, t] -> y[b][o][t] ----
    const int gq = lane >> 2, qq = lane & 3;
    #pragma unroll
    for (int mb = 0; mb < 4; mb++) {
        #pragma unroll
        for (int nb = 0; nb < 4; nb++) {
            const int o = mb * 16 + gq;
            const int t = t0 + wid * 32 + nb * 8 + qq * 2;
            float2 v0 = make_float2(acc[mb][nb][0], acc[mb][nb][1]);
            float2 v1 = make_float2(acc[mb][nb][2], acc[mb][nb][3]);
            *reinterpret_cast<float2*>(&y[((size_t)b * NCH + o) * TLEN + t]) = v0;
            *reinterpret_cast<float2*>(&y[((size_t)b * NCH + o + 8) * TLEN + t]) = v1;
        }
    }
}

extern "C" void kernel_launch(void* const* d_in, const int* in_sizes, int n_in,
                              void* d_out, int out_size) {
    const float* x = (const float*)d_in[0];
    const float* W = (const float*)d_in[1];
    float* y = (float*)d_out;
    (void)in_sizes; (void)n_in; (void)out_size;
    cudaFuncSetAttribute(conv_mma, cudaFuncAttributeMaxDynamicSharedMemorySize, SMEMSZ);
    prep_x<<<dim3(TP / 128, TB), 256>>>(x);
    prep_w<<<(KW * NCH * 32 + 255) / 256, 256>>>(W);
    conv_mma<<<dim3(TLEN / TILE_T, TB), 256, SMEMSZ>>>(y);
}

// round 10
// speedup vs baseline: 14.9539x; 1.4644x over previous
#include <cuda_runtime.h>
#include <cstdint>

#define BATCH  8
#define NCH    64
#define TLEN   16384
#define KW     127
#define NF     512
#define NH     386            // NF - KW + 1 valid outputs per segment
#define NSEG   43             // ceil(TLEN / NH)
#define NBINS  257
#define BS_TOT (BATCH * NSEG) // 344

__device__ __align__(16) float2 g_Xs[(size_t)NBINS * BS_TOT * NCH]; // [f][bs][i]
__device__ __align__(16) float2 g_Ws[(size_t)NBINS * NCH * NCH];    // [f][i][o]
__device__ __align__(16) float2 g_Ys[(size_t)NBINS * BS_TOT * NCH]; // [f][bs][o]

__device__ __forceinline__ float2 cmul(float2 a, float2 b) {
    return make_float2(a.x * b.x - a.y * b.y, a.x * b.y + a.y * b.x);
}

// 4 interleaved radix-2 Stockham FFT-512 (natural order in/out). Result in B.
// Caller must __syncthreads() after filling A. tw[m] = exp(sign*2*pi*i*m/512).
__device__ __forceinline__ void fft512x4(float2 (*A)[NF], float2 (*B)[NF],
                                         const float2* tw, int tid) {
    float2 (*S)[NF] = A; float2 (*D)[NF] = B;
    #pragma unroll
    for (int st = 0; st < 9; st++) {
        const int Ns = 1 << st, mask = Ns - 1;
        const float2 w = tw[(tid & mask) << (8 - st)];
        const int idx = ((tid >> st) << (st + 1)) | (tid & mask);
        #pragma unroll
        for (int u = 0; u < 4; u++) {
            float2 v0 = S[u][tid], v1 = cmul(S[u][tid + 256], w);
            D[u][idx]      = make_float2(v0.x + v1.x, v0.y + v1.y);
            D[u][idx + Ns] = make_float2(v0.x - v1.x, v0.y - v1.y);
        }
        __syncthreads();
        float2 (*t)[NF] = S; S = D; D = t;
    }
}
__device__ __forceinline__ void build_tw(float2* tw, int tid, float sgn) {
    float a = sgn * (6.28318530717958647692f / NF) * (float)tid;
    float s, c; sincosf(a, &s, &c);
    tw[tid] = make_float2(c, s);
}

// ---- W spectra: blocks (i, pg); 4 FFTs over o-pairs ----
__global__ void __launch_bounds__(256) fft_w(const float* __restrict__ W) {
    __shared__ float2 A[4][NF], B[4][NF], tw[256];
    const int tid = threadIdx.x;
    const int i = blockIdx.x >> 3, pg = blockIdx.x & 7;
    build_tw(tw, tid, -1.f);
    #pragma unroll
    for (int u = 0; u < 4; u++) {
        const int o0 = ((pg << 2) + u) << 1;
        for (int n = tid; n < NF; n += 256) {
            float re = (n < KW) ? W[((size_t)o0 * NCH + i) * KW + n] : 0.f;
            float im = (n < KW) ? W[((size_t)(o0 + 1) * NCH + i) * KW + n] : 0.f;
            A[u][n] = make_float2(re, im);
        }
    }
    __syncthreads();
    fft512x4(A, B, tw, tid);
    #pragma unroll
    for (int u = 0; u < 4; u++) {
        const int o0 = ((pg << 2) + u) << 1;
        for (int f = tid; f < NBINS; f += 256) {
            float2 zf = B[u][f], zc = B[u][(NF - f) & (NF - 1)];
            g_Ws[((size_t)f * NCH + i) * NCH + o0] =
                make_float2(0.5f * (zf.x + zc.x), 0.5f * (zf.y - zc.y));
            g_Ws[((size_t)f * NCH + i) * NCH + o0 + 1] =
                make_float2(0.5f * (zf.y + zc.y), 0.5f * (zc.x - zf.x));
        }
    }
}

// ---- x spectra: blocks (b, s, pg); 4 FFTs over cin-pairs ----
__global__ void __launch_bounds__(256) fft_x(const float* __restrict__ x) {
    __shared__ float2 A[4][NF], B[4][NF], tw[256];
    const int tid = threadIdx.x;
    const int b = blockIdx.x / 344, r2 = blockIdx.x % 344;
    const int s = r2 >> 3, pg = r2 & 7;
    build_tw(tw, tid, -1.f);
    #pragma unroll
    for (int u = 0; u < 4; u++) {
        const int i0 = ((pg << 2) + u) << 1;
        const int tbase = s * NH - 63;
        for (int n = tid; n < NF; n += 256) {
            const int t = tbase + n;
            const bool ok = (t >= 0) && (t < TLEN);
            float re = ok ? x[((size_t)b * NCH + i0) * TLEN + t] : 0.f;
            float im = ok ? x[((size_t)b * NCH + i0 + 1) * TLEN + t] : 0.f;
            A[u][n] = make_float2(re, im);
        }
    }
    __syncthreads();
    fft512x4(A, B, tw, tid);
    const int bs = b * NSEG + s;
    #pragma unroll
    for (int u = 0; u < 4; u++) {
        const int i0 = ((pg << 2) + u) << 1;
        for (int f = tid; f < NBINS; f += 256) {
            float2 zf = B[u][f], zc = B[u][(NF - f) & (NF - 1)];
            g_Xs[((size_t)f * BS_TOT + bs) * NCH + i0] =
                make_float2(0.5f * (zf.x + zc.x), 0.5f * (zf.y - zc.y));
            g_Xs[((size_t)f * BS_TOT + bs) * NCH + i0 + 1] =
                make_float2(0.5f * (zf.y + zc.y), 0.5f * (zc.x - zf.x));
        }
    }
}

// ---- per-bin complex GEMM: Y[f][bs][o] = sum_i X[f][bs][i] * W[f][i][o] ----
#define CG_SMEM (64 * 64 * 8 + 32 * 66 * 8)   // 49664
__global__ void __launch_bounds__(256) cgemm_k() {
    extern __shared__ float2 dsm[];
    float2* sW = dsm;                                    // [64][64]
    float2 (*sX)[66] = (float2(*)[66])(dsm + 4096);      // [32][66] padded
    const int tid = threadIdx.x;
    const int f = blockIdx.x, bs0 = blockIdx.y << 5;
    {   // load W bin (float4 bulk) and X tile
        const float4* s4 = (const float4*)(g_Ws + (size_t)f * NCH * NCH);
        float4* d4 = (float4*)sW;
        #pragma unroll
        for (int e = tid; e < 2048; e += 256) d4[e] = s4[e];
        for (int e = tid; e < 2048; e += 256) {
            const int r = e >> 6, i = e & 63, bs = bs0 + r;
            sX[r][i] = (bs < BS_TOT)
                     ? g_Xs[((size_t)f * BS_TOT + bs) * NCH + i]
                     : make_float2(0.f, 0.f);
        }
    }
    __syncthreads();
    const int r = tid >> 3, c = tid & 7;
    float ar[8], ai[8];
    #pragma unroll
    for (int oo = 0; oo < 8; oo++) { ar[oo] = 0.f; ai[oo] = 0.f; }
    #pragma unroll 4
    for (int i = 0; i < NCH; i++) {
        const float2 xa = sX[r][i];
        #pragma unroll
        for (int oo = 0; oo < 8; oo++) {
            const float2 w = sW[i * 64 + c + (oo << 3)];
            ar[oo] += xa.x * w.x - xa.y * w.y;
            ai[oo] += xa.x * w.y + xa.y * w.x;
        }
    }
    const int bs = bs0 + r;
    if (bs < BS_TOT) {
        #pragma unroll
        for (int oo = 0; oo < 8; oo++)
            g_Ys[((size_t)f * BS_TOT + bs) * NCH + c + (oo << 3)] =
                make_float2(ar[oo], ai[oo]);
    }
}

// ---- inverse FFT + centered crop: blocks (b, s, pg); 4 iFFTs over o-pairs ----
__global__ void __launch_bounds__(256) ifft_y(float* __restrict__ y) {
    __shared__ float2 A[4][NF], B[4][NF], tw[256];
    const int tid = threadIdx.x;
    const int b = blockIdx.x / 344, r2 = blockIdx.x % 344;
    const int s = r2 >> 3, pg = r2 & 7;
    build_tw(tw, tid, 1.f);
    const int bs = b * NSEG + s;
    #pragma unroll
    for (int u = 0; u < 4; u++) {
        const int o0 = ((pg << 2) + u) << 1;
        for (int f = tid; f < NBINS; f += 256) {
            const float4 yy = *(const float4*)
                &g_Ys[((size_t)f * BS_TOT + bs) * NCH + o0];  // y0=(x,y) y1=(z,w)
            A[u][f] = make_float2(yy.x - yy.w, yy.y + yy.z);  // y0 + i*y1
            if (f >= 1 && f < 256)                             // conj mirror
                A[u][NF - f] = make_float2(yy.x + yy.w, yy.z - yy.y);
        }
    }
    __syncthreads();
    fft512x4(A, B, tw, tid);
    const float sc = 1.f / NF;
    #pragma unroll
    for (int u = 0; u < 4; u++) {
        const int o0 = ((pg << 2) + u) << 1;
        for (int n = KW - 1 + tid; n < NF; n += 256) {   // n in [126, 512)
            const int t = s * NH + n - (KW - 1);
            if (t < TLEN) {
                y[((size_t)b * NCH + o0) * TLEN + t]     = B[u][n].x * sc;
                y[((size_t)b * NCH + o0 + 1) * TLEN + t] = B[u][n].y * sc;
            }
        }
    }
}

extern "C" void kernel_launch(void* const* d_in, const int* in_sizes, int n_in,
                              void* d_out, int out_size) {
    const float* x = (const float*)d_in[0];   // [B][CIN][T]
    const float* W = (const float*)d_in[1];   // [COUT][CIN][K]
    float* y       = (float*)d_out;           // [B][COUT][T]
    (void)in_sizes; (void)n_in; (void)out_size;
    cudaFuncSetAttribute(cgemm_k, cudaFuncAttributeMaxDynamicSharedMemorySize,
                         CG_SMEM);
    fft_w<<<512, 256>>>(W);                   // 2048 packed FFTs
    fft_x<<<BATCH * 344, 256>>>(x);           // 11008 packed FFTs
    cgemm_k<<<dim3(NBINS, 11), 256, CG_SMEM>>>();
    ifft_y<<<BATCH * 344, 256>>>(y);          // 11008 packed iFFTs
}